// round 1
// baseline (speedup 1.0000x reference)
#include <cuda_runtime.h>
#include <cuda_bf16.h>
#include <stdint.h>

// Problem constants (fixed by the dataset)
#define N_NODES 100000
#define NE      1600000
#define IN_DIM  256
#define HID     128

// ---------------- scratch (static device globals; no allocation) ------------
__device__ int   d_src32[NE];
__device__ int   d_dst32[NE];
__device__ int   d_srcs[NE];       // CSR-permuted source indices (by dst)
__device__ int   d_cnt[N_NODES];
__device__ int   d_rowptr[N_NODES];
__device__ int   d_cursor[N_NODES];
__device__ float d_dinv[N_NODES];
__device__ float d_h[(size_t)N_NODES * HID];
__device__ float d_t[(size_t)N_NODES * HID];
__device__ int   g_is64;

// ---------------- edge dtype detection + conversion -------------------------
// If edge_index is int64, every odd 32-bit word is the (zero) high half,
// because values are in [0, 100000). If int32, odd words are random node ids.
__global__ void k_detect(const int* __restrict__ w) {
    int ok = 1;
    for (int i = 0; i < 64; i++) {
        if (w[2 * i + 1] != 0) { ok = 0; break; }
    }
    g_is64 = ok;
}

__global__ void k_convert(const void* __restrict__ ei) {
    int e = blockIdx.x * blockDim.x + threadIdx.x;
    if (e >= NE) return;
    if (g_is64) {
        const long long* p = (const long long*)ei;
        d_src32[e] = (int)p[e];
        d_dst32[e] = (int)p[e + NE];
    } else {
        const int* p = (const int*)ei;
        d_src32[e] = p[e];
        d_dst32[e] = p[e + NE];
    }
}

// ---------------- CSR build --------------------------------------------------
__global__ void k_zero_cnt() {
    int i = blockIdx.x * blockDim.x + threadIdx.x;
    if (i < N_NODES) d_cnt[i] = 0;
}

__global__ void k_count() {
    int e = blockIdx.x * blockDim.x + threadIdx.x;
    if (e < NE) atomicAdd(&d_cnt[d_dst32[e]], 1);
}

// Single-block exclusive scan of counts -> rowptr (+cursor copy) + dinv.
// 1024 threads, each owns a contiguous chunk of ceil(N/1024) nodes.
__global__ void k_scan() {
    __shared__ int sums[1024];
    const int tid = threadIdx.x;
    const int CH = (N_NODES + 1023) / 1024;
    const int base = tid * CH;

    int s = 0;
    for (int i = 0; i < CH; i++) {
        int idx = base + i;
        if (idx < N_NODES) s += d_cnt[idx];
    }
    sums[tid] = s;
    __syncthreads();
    // Hillis-Steele inclusive scan
    for (int off = 1; off < 1024; off <<= 1) {
        int v = (tid >= off) ? sums[tid - off] : 0;
        __syncthreads();
        sums[tid] += v;
        __syncthreads();
    }
    int run = (tid == 0) ? 0 : sums[tid - 1];
    for (int i = 0; i < CH; i++) {
        int idx = base + i;
        if (idx < N_NODES) {
            d_rowptr[idx] = run;
            d_cursor[idx] = run;
            int c = d_cnt[idx];
            run += c;
            d_dinv[idx] = rsqrtf((float)(c + 1)); // +1 = self loop
        }
    }
}

__global__ void k_fill() {
    int e = blockIdx.x * blockDim.x + threadIdx.x;
    if (e >= NE) return;
    int dd = d_dst32[e];
    int pos = atomicAdd(&d_cursor[dd], 1);
    d_srcs[pos] = d_src32[e];
}

// ---------------- GEMM: C[M,128] = act(A[M,K] @ W[K,128] + b) ---------------
// 256 threads/block; block computes 64 rows x 128 cols.
// warp w -> rows [w*8, w*8+8), lane -> cols [lane*4, lane*4+4).
template <int K, bool RELU, bool BIAS>
__global__ void __launch_bounds__(256) k_gemm(const float* __restrict__ A,
                                              const float* __restrict__ W,
                                              const float* __restrict__ bias,
                                              float* __restrict__ C, int M) {
    __shared__ float  sA[64][32];
    __shared__ float4 sW[32][32];

    const int tid  = threadIdx.x;
    const int warp = tid >> 5;
    const int lane = tid & 31;
    const int row0 = blockIdx.x * 64;

    float4 acc[8];
#pragma unroll
    for (int r = 0; r < 8; r++) acc[r] = make_float4(0.f, 0.f, 0.f, 0.f);

    for (int kc = 0; kc < K; kc += 32) {
        // A tile: 64 rows x 32 k = 512 float4
#pragma unroll
        for (int i = 0; i < 2; i++) {
            int idx = tid + i * 256;        // 0..511
            int r = idx >> 3, c = idx & 7;  // c in float4 units
            int grow = row0 + r;
            float4 v = make_float4(0.f, 0.f, 0.f, 0.f);
            if (grow < M)
                v = *(const float4*)(A + (size_t)grow * K + kc + c * 4);
            *(float4*)(&sA[r][c * 4]) = v;
        }
        // W tile: 32 k x 128 cols = 1024 float4
#pragma unroll
        for (int i = 0; i < 4; i++) {
            int idx = tid + i * 256;         // 0..1023
            int kr = idx >> 5, c = idx & 31;
            sW[kr][c] = *(const float4*)(W + (size_t)(kc + kr) * 128 + c * 4);
        }
        __syncthreads();
#pragma unroll
        for (int kk = 0; kk < 32; kk++) {
            float4 wv = sW[kk][lane];
#pragma unroll
            for (int r = 0; r < 8; r++) {
                float a = sA[warp * 8 + r][kk];
                acc[r].x += a * wv.x;
                acc[r].y += a * wv.y;
                acc[r].z += a * wv.z;
                acc[r].w += a * wv.w;
            }
        }
        __syncthreads();
    }

    float4 bv = make_float4(0.f, 0.f, 0.f, 0.f);
    if (BIAS) bv = *(const float4*)(bias + lane * 4);
#pragma unroll
    for (int r = 0; r < 8; r++) {
        int grow = row0 + warp * 8 + r;
        if (grow < M) {
            float4 o;
            o.x = acc[r].x + bv.x;
            o.y = acc[r].y + bv.y;
            o.z = acc[r].z + bv.z;
            o.w = acc[r].w + bv.w;
            if (RELU) {
                o.x = fmaxf(o.x, 0.f); o.y = fmaxf(o.y, 0.f);
                o.z = fmaxf(o.z, 0.f); o.w = fmaxf(o.w, 0.f);
            }
            *(float4*)(C + (size_t)grow * 128 + lane * 4) = o;
        }
    }
}

// ---------------- GCN aggregate: warp per destination node ------------------
// h_new[d] = dinv[d] * ( t[d]*dinv[d] + sum_j t[src_j]*dinv[src_j] ) + b
__global__ void __launch_bounds__(256) k_aggregate(const float* __restrict__ t,
                                                   const float* __restrict__ b,
                                                   float* __restrict__ hout) {
    const int wid  = (blockIdx.x * blockDim.x + threadIdx.x) >> 5;
    const int lane = threadIdx.x & 31;
    if (wid >= N_NODES) return;
    const int d = wid;

    const float4* t4 = (const float4*)t;
    const float dd = d_dinv[d];

    float4 acc = t4[d * 32 + lane];   // self term
    acc.x *= dd; acc.y *= dd; acc.z *= dd; acc.w *= dd;

    const int beg = d_rowptr[d];
    const int num = d_cnt[d];
    for (int j = 0; j < num; j++) {
        int s = d_srcs[beg + j];
        float ds = d_dinv[s];
        float4 v = t4[s * 32 + lane];
        acc.x += v.x * ds; acc.y += v.y * ds;
        acc.z += v.z * ds; acc.w += v.w * ds;
    }

    float4 bv = ((const float4*)b)[lane];
    float4 o;
    o.x = acc.x * dd + bv.x;
    o.y = acc.y * dd + bv.y;
    o.z = acc.z * dd + bv.z;
    o.w = acc.w * dd + bv.w;
    ((float4*)hout)[(size_t)d * 32 + lane] = o;
}

// ---------------- head: out[N,2] = h @ Wh + bh ------------------------------
__global__ void __launch_bounds__(256) k_head(const float* __restrict__ h,
                                              const float* __restrict__ Wh,
                                              const float* __restrict__ bh,
                                              float* __restrict__ out) {
    const int wid  = (blockIdx.x * blockDim.x + threadIdx.x) >> 5;
    const int lane = threadIdx.x & 31;
    if (wid >= N_NODES) return;

    float4 v = ((const float4*)(h + (size_t)wid * 128))[lane];
    // Wh is [128,2] row-major -> 8 consecutive floats cover lane's 4 k's
    float4 w0 = *(const float4*)(Wh + lane * 8);
    float4 w1 = *(const float4*)(Wh + lane * 8 + 4);
    float p0 = v.x * w0.x + v.y * w0.z + v.z * w1.x + v.w * w1.z;
    float p1 = v.x * w0.y + v.y * w0.w + v.z * w1.y + v.w * w1.w;
#pragma unroll
    for (int off = 16; off; off >>= 1) {
        p0 += __shfl_xor_sync(0xFFFFFFFFu, p0, off);
        p1 += __shfl_xor_sync(0xFFFFFFFFu, p1, off);
    }
    if (lane == 0) {
        out[wid * 2 + 0] = p0 + bh[0];
        out[wid * 2 + 1] = p1 + bh[1];
    }
}

// ---------------- launch -----------------------------------------------------
extern "C" void kernel_launch(void* const* d_in, const int* in_sizes, int n_in,
                              void* d_out, int out_size) {
    const void*  ei = d_in[0];                       // edge_index [2,E] (int32 or int64)
    const float* x  = (const float*)d_in[1];         // [N, 256]
    const float* Wi = (const float*)d_in[2];         // [256,128]
    const float* bi = (const float*)d_in[3];
    const float* W1 = (const float*)d_in[4];         // [128,128]
    const float* b1 = (const float*)d_in[5];
    const float* W2 = (const float*)d_in[6];
    const float* b2 = (const float*)d_in[7];
    const float* Wh = (const float*)d_in[8];         // [128,2]
    const float* bh = (const float*)d_in[9];
    float* out = (float*)d_out;

    float *h, *t;
    cudaGetSymbolAddress((void**)&h, d_h);
    cudaGetSymbolAddress((void**)&t, d_t);

    const int EB = (NE + 255) / 256;
    const int NB = (N_NODES + 255) / 256;
    const int GB = (N_NODES + 63) / 64;       // GEMM blocks (64 rows each)
    const int WB = (N_NODES + 7) / 8;         // warp-per-node blocks (8 warps each)

    // 1. normalize edge dtype
    k_detect<<<1, 1>>>((const int*)ei);
    k_convert<<<EB, 256>>>(ei);

    // 2. CSR by destination + degree normalization
    k_zero_cnt<<<NB, 256>>>();
    k_count<<<EB, 256>>>();
    k_scan<<<1, 1024>>>();
    k_fill<<<EB, 256>>>();

    // 3. node init: h = relu(x @ Wi + bi)
    k_gemm<IN_DIM, true, true><<<GB, 256>>>(x, Wi, bi, h, N_NODES);

    // 4. GCN layer 1: t = h @ W1 ; h = aggregate(t) + b1
    k_gemm<HID, false, false><<<GB, 256>>>(h, W1, nullptr, t, N_NODES);
    k_aggregate<<<WB, 256>>>(t, b1, h);

    // 5. GCN layer 2
    k_gemm<HID, false, false><<<GB, 256>>>(h, W2, nullptr, t, N_NODES);
    k_aggregate<<<WB, 256>>>(t, b2, h);

    // 6. head
    k_head<<<WB, 256>>>(h, Wh, bh, out);
}